// round 7
// baseline (speedup 1.0000x reference)
#include <cuda_runtime.h>
#include <math.h>

#define PS      16
#define EMB     64
#define TP      32            // patches per block
#define WSTR    68            // e-tile stride (floats), 16B-aligned, odd/4 padding
#define PSTR    36            // p-tile stride (floats)
#define NPATCH  98304
#define PPB     3072          // patches per batch image

// dynamic shared layout (floats):
//   wT   [256][WSTR]   -> wT[i*WSTR + e], e in [0,64)     : 69632 B
//   sT   [256][PSTR]   -> sT[i*PSTR + p], p in [0,32)     : 36864 B
//   masks[32][8] uint                                     :  1024 B
//   bs   [64]                                             :   256 B
#define SMEM_BYTES (256*WSTR*4 + 256*PSTR*4 + 32*8*4 + 64*4)

__global__ __launch_bounds__(256, 2)
void fractal_fused_kernel(const float* __restrict__ x,
                          const float* __restrict__ W,
                          const float* __restrict__ bias,
                          float* __restrict__ emb,
                          float* __restrict__ frac)
{
    extern __shared__ float sh[];
    float*    wT    = sh;
    float*    sT    = sh + 256 * WSTR;
    unsigned* masks = (unsigned*)(sT + 256 * PSTR);
    float*    bs    = (float*)(masks + 32 * 8);

    const int t = threadIdx.x;
    const int base_patch = blockIdx.x * TP;

    if (t < 64) bs[t] = bias[t];

    // ---- stage W transposed: iteration j loads row e=j (coalesced) ----
    #pragma unroll 8
    for (int j = 0; j < 64; ++j) {
        wT[t * WSTR + j] = W[j * 256 + t];
    }

    // ---- stage pixels + occupancy masks: iteration j = local patch j ----
    const int r  = t >> 4;       // within-patch row
    const int cc = t & 15;       // within-patch col
    #pragma unroll 4
    for (int j = 0; j < TP; ++j) {
        int pg   = base_patch + j;
        int b    = pg / PPB;
        int rem  = pg - b * PPB;
        int tile = rem / 3;
        int c    = rem - tile * 3;
        int th   = tile >> 5;
        int tw   = tile & 31;
        size_t addr = (((size_t)(b * 3 + c) * 512) + (size_t)(th * PS + r)) * 512
                      + (size_t)(tw * PS + cc);
        float v = x[addr];
        sT[t * PSTR + j] = v;
        unsigned bal = __ballot_sync(0xffffffffu, v > 0.1f);
        if ((t & 31) == 0) masks[j * 8 + (t >> 5)] = bal;
    }
    __syncthreads();

    // ---- fractal dimension: threads 0..31, one patch each ----
    if (t < TP) {
        unsigned m[8];
        #pragma unroll
        for (int w = 0; w < 8; ++w) m[w] = masks[t * 8 + w];

        int n1 = 0, n2 = 0, n3 = 0, n4;
        // scale 2: 2x2 boxes. m[i] holds rows 2i (lo16) | 2i+1 (hi16)
        #pragma unroll
        for (int i = 0; i < 8; ++i) {
            unsigned rp = (m[i] & 0xffffu) | (m[i] >> 16);
            n1 += __popc((rp | (rp >> 1)) & 0x5555u);
        }
        // scale 4: 4x4 boxes
        #pragma unroll
        for (int i = 0; i < 4; ++i) {
            unsigned q = m[2 * i] | m[2 * i + 1];
            q = (q & 0xffffu) | (q >> 16);
            q = q | (q >> 1) | (q >> 2) | (q >> 3);
            n2 += __popc(q & 0x1111u);
        }
        // scale 8: 8x8 boxes
        #pragma unroll
        for (int i = 0; i < 2; ++i) {
            unsigned o = m[4*i] | m[4*i+1] | m[4*i+2] | m[4*i+3];
            o = (o & 0xffffu) | (o >> 16);
            o = o | (o >> 1) | (o >> 2) | (o >> 3) | (o >> 4) | (o >> 5) | (o >> 6) | (o >> 7);
            n3 += __popc(o & 0x0101u);
        }
        // scale 16: one box
        {
            unsigned a = 0;
            #pragma unroll
            for (int w = 0; w < 8; ++w) a |= m[w];
            n4 = (a != 0) ? 1 : 0;
        }
        float slope = 0.3f * (log2f((float)n1) - log2f((float)n4))
                    + 0.1f * (log2f((float)n2) - log2f((float)n3));
        frac[base_patch + t] = slope;
    }

    // ---- GEMM: 64e x 32p tile, micro-tile 4e x 2p per thread ----
    const int pe = t >> 4;        // 0..15 -> e0 = 4*pe
    const int pg = t & 15;        // 0..15 -> p0 = 2*pg
    const int e0 = pe * 4;
    const int p0 = pg * 2;

    float a00 = 0.f, a01 = 0.f, a10 = 0.f, a11 = 0.f;
    float a20 = 0.f, a21 = 0.f, a30 = 0.f, a31 = 0.f;

    const float4* wp = (const float4*)(wT + e0);
    const float2* sp = (const float2*)(sT + p0);

    #pragma unroll 8
    for (int i = 0; i < 256; ++i) {
        float4 wv = *(const float4*)((const float*)wp + i * WSTR);
        float2 sv = *(const float2*)((const float*)sp + i * PSTR);
        a00 = fmaf(wv.x, sv.x, a00);  a01 = fmaf(wv.x, sv.y, a01);
        a10 = fmaf(wv.y, sv.x, a10);  a11 = fmaf(wv.y, sv.y, a11);
        a20 = fmaf(wv.z, sv.x, a20);  a21 = fmaf(wv.z, sv.y, a21);
        a30 = fmaf(wv.w, sv.x, a30);  a31 = fmaf(wv.w, sv.y, a31);
    }

    float b0 = bs[e0 + 0], b1 = bs[e0 + 1], b2 = bs[e0 + 2], b3 = bs[e0 + 3];
    {
        float4 o;
        o.x = a00 + b0; o.y = a10 + b1; o.z = a20 + b2; o.w = a30 + b3;
        *(float4*)&emb[(size_t)(base_patch + p0) * EMB + e0] = o;
    }
    {
        float4 o;
        o.x = a01 + b0; o.y = a11 + b1; o.z = a21 + b2; o.w = a31 + b3;
        *(float4*)&emb[(size_t)(base_patch + p0 + 1) * EMB + e0] = o;
    }
}

// ---- harmonics FINAL: reconstructed eigh basis ----
// Basis functions: w_{jk}[a*16+b] = (2/17) sin((a+1) j pi/17) sin((b+1) k pi/17)
// Each ref column = cA*w_{jA,kA} + cB*w_{jB,kB}   (measured over rounds 1-6):
//  col0: -w11
//  col1: (w12+w21)/sqrt2      col2: (w12-w21)/sqrt2
//  col3: -w22
//  col4: c*w13 - s*w31        col5: s*w13 + c*w31     (rotation, c=0.7106526, s=0.7035431)
//  col6: m11*w23 + m12*w32    col7: m12*w23 - m11*w32 (reflection, 0.6690689, -0.7432122)
//  col8: (-w14+w41)/sqrt2     col9: (w14+w41)/sqrt2
__constant__ int   CJA[10] = {1, 1, 1, 2, 1, 1, 2, 2, 1, 1};
__constant__ int   CKA[10] = {1, 2, 2, 2, 3, 3, 3, 3, 4, 4};
__constant__ float CCA[10] = {-1.0f, 0.70710678f, 0.70710678f, -1.0f,
                              0.7106526f, 0.7035431f, 0.6690689f, -0.7432122f,
                              -0.70710678f, 0.70710678f};
__constant__ int   CJB[10] = {1, 2, 2, 2, 3, 3, 3, 3, 4, 4};
__constant__ int   CKB[10] = {1, 1, 1, 2, 1, 1, 2, 2, 1, 1};
__constant__ float CCB[10] = {0.0f, 0.70710678f, -0.70710678f, 0.0f,
                              -0.7035431f, 0.7106526f, -0.7432122f, -0.6690689f,
                              0.70710678f, 0.70710678f};

__global__ void harmonics_kernel(float* __restrict__ out)
{
    int h = blockIdx.x;          // 0..9
    int m = threadIdx.x;         // 0..255
    int a = m >> 4;
    int b = m & 15;
    const float norm = 0.11764705882352941f;   // 2/17
    const float pi17 = 0.18479956785822313f;   // pi/17
    float wa = norm * sinf((float)((a + 1) * CJA[h]) * pi17)
                    * sinf((float)((b + 1) * CKA[h]) * pi17);
    float wb = norm * sinf((float)((a + 1) * CJB[h]) * pi17)
                    * sinf((float)((b + 1) * CKB[h]) * pi17);
    out[m * 10 + h] = CCA[h] * wa + CCB[h] * wb;
}

extern "C" void kernel_launch(void* const* d_in, const int* in_sizes, int n_in,
                              void* d_out, int out_size)
{
    const float* x    = (const float*)d_in[0];
    const float* W    = (const float*)d_in[1];
    const float* bias = (const float*)d_in[2];

    float* out  = (float*)d_out;
    float* emb  = out;
    float* frac = out + (size_t)NPATCH * EMB;
    float* harm = frac + NPATCH;

    cudaFuncSetAttribute(fractal_fused_kernel,
                         cudaFuncAttributeMaxDynamicSharedMemorySize, SMEM_BYTES);
    fractal_fused_kernel<<<NPATCH / TP, 256, SMEM_BYTES>>>(x, W, bias, emb, frac);
    harmonics_kernel<<<10, 256>>>(harm);
}

// round 10
// speedup vs baseline: 1.0375x; 1.0375x over previous
#include <cuda_runtime.h>
#include <math.h>

#define PS      16
#define EMB     64
#define TP      32            // patches per block
#define WSTR    68            // e-tile stride (floats), 16B-aligned, odd/4 padding
#define PSTR    36            // p-tile stride (floats)
#define NPATCH  98304
#define PPB     3072          // patches per batch image

// dynamic shared layout (floats):
//   wT   [256][WSTR]   -> wT[i*WSTR + e], e in [0,64)     : 69632 B
//   sT   [256][PSTR]   -> sT[i*PSTR + p], p in [0,32)     : 36864 B
//   masks[32][8] uint                                     :  1024 B
//   bs   [64]                                             :   256 B
#define SMEM_BYTES (256*WSTR*4 + 256*PSTR*4 + 32*8*4 + 64*4)

// packed fp32x2 FMA: d = a*b + d  (lane-wise IEEE fp32, bit-identical to fmaf)
#define FMA_F32X2(d, a, b) \
    asm("fma.rn.f32x2 %0, %1, %2, %3;" : "=l"(d) : "l"(a), "l"(b), "l"(d))

// ---- harmonics: reconstructed eigh basis (measured rounds 1-6) ----
__constant__ int   CJA[10] = {1, 1, 1, 2, 1, 1, 2, 2, 1, 1};
__constant__ int   CKA[10] = {1, 2, 2, 2, 3, 3, 3, 3, 4, 4};
__constant__ float CCA[10] = {-1.0f, 0.70710678f, 0.70710678f, -1.0f,
                              0.7106526f, 0.7035431f, 0.6690689f, -0.7432122f,
                              -0.70710678f, 0.70710678f};
__constant__ int   CJB[10] = {1, 2, 2, 2, 3, 3, 3, 3, 4, 4};
__constant__ int   CKB[10] = {1, 1, 1, 2, 1, 1, 2, 2, 1, 1};
__constant__ float CCB[10] = {0.0f, 0.70710678f, -0.70710678f, 0.0f,
                              -0.7035431f, 0.7106526f, -0.7432122f, -0.6690689f,
                              0.70710678f, 0.70710678f};

__global__ __launch_bounds__(256, 2)
void fractal_fused_kernel(const float* __restrict__ x,
                          const float* __restrict__ W,
                          const float* __restrict__ bias,
                          float* __restrict__ emb,
                          float* __restrict__ frac,
                          float* __restrict__ harm)
{
    extern __shared__ float sh[];
    float*    wT    = sh;
    float*    sT    = sh + 256 * WSTR;
    unsigned* masks = (unsigned*)(sT + 256 * PSTR);
    float*    bs    = (float*)(masks + 32 * 8);

    const int t = threadIdx.x;
    const int base_patch = blockIdx.x * TP;

    // ---- harmonics folded into blocks 0..9 (one element per thread) ----
    if (blockIdx.x < 10) {
        int h = blockIdx.x;
        int a = t >> 4;
        int b = t & 15;
        const float norm = 0.11764705882352941f;   // 2/17
        const float pi17 = 0.18479956785822313f;   // pi/17
        float wa = norm * sinf((float)((a + 1) * CJA[h]) * pi17)
                        * sinf((float)((b + 1) * CKA[h]) * pi17);
        float wb = norm * sinf((float)((a + 1) * CJB[h]) * pi17)
                        * sinf((float)((b + 1) * CKB[h]) * pi17);
        harm[t * 10 + h] = CCA[h] * wa + CCB[h] * wb;
    }

    if (t < 64) bs[t] = bias[t];

    // ---- stage W transposed: iteration j loads row e=j (coalesced) ----
    #pragma unroll 8
    for (int j = 0; j < 64; ++j) {
        wT[t * WSTR + j] = W[j * 256 + t];
    }

    // ---- stage pixels + occupancy masks: iteration j = local patch j ----
    const int r  = t >> 4;       // within-patch row
    const int cc = t & 15;       // within-patch col
    #pragma unroll 4
    for (int j = 0; j < TP; ++j) {
        int pg   = base_patch + j;
        int b    = pg / PPB;
        int rem  = pg - b * PPB;
        int tile = rem / 3;
        int c    = rem - tile * 3;
        int th   = tile >> 5;
        int tw   = tile & 31;
        size_t addr = (((size_t)(b * 3 + c) * 512) + (size_t)(th * PS + r)) * 512
                      + (size_t)(tw * PS + cc);
        float v = x[addr];
        sT[t * PSTR + j] = v;
        unsigned bal = __ballot_sync(0xffffffffu, v > 0.1f);
        if ((t & 31) == 0) masks[j * 8 + (t >> 5)] = bal;
    }
    __syncthreads();

    // ---- fractal dimension: threads 0..31, one patch each ----
    if (t < TP) {
        unsigned m[8];
        #pragma unroll
        for (int w = 0; w < 8; ++w) m[w] = masks[t * 8 + w];

        int n1 = 0, n2 = 0, n3 = 0, n4;
        // scale 2: 2x2 boxes. m[i] holds rows 2i (lo16) | 2i+1 (hi16)
        #pragma unroll
        for (int i = 0; i < 8; ++i) {
            unsigned rp = (m[i] & 0xffffu) | (m[i] >> 16);
            n1 += __popc((rp | (rp >> 1)) & 0x5555u);
        }
        // scale 4: 4x4 boxes
        #pragma unroll
        for (int i = 0; i < 4; ++i) {
            unsigned q = m[2 * i] | m[2 * i + 1];
            q = (q & 0xffffu) | (q >> 16);
            q = q | (q >> 1) | (q >> 2) | (q >> 3);
            n2 += __popc(q & 0x1111u);
        }
        // scale 8: 8x8 boxes
        #pragma unroll
        for (int i = 0; i < 2; ++i) {
            unsigned o = m[4*i] | m[4*i+1] | m[4*i+2] | m[4*i+3];
            o = (o & 0xffffu) | (o >> 16);
            o = o | (o >> 1) | (o >> 2) | (o >> 3) | (o >> 4) | (o >> 5) | (o >> 6) | (o >> 7);
            n3 += __popc(o & 0x0101u);
        }
        // scale 16: one box
        {
            unsigned a = 0;
            #pragma unroll
            for (int w = 0; w < 8; ++w) a |= m[w];
            n4 = (a != 0) ? 1 : 0;
        }
        float slope = 0.3f * (log2f((float)n1) - log2f((float)n4))
                    + 0.1f * (log2f((float)n2) - log2f((float)n3));
        frac[base_patch + t] = slope;
    }

    // ---- GEMM: 64e x 32p tile, micro-tile 4e x 2p per thread, packed f32x2 ----
    // w pairs (e0,e1),(e2,e3) are contiguous in wT -> LDS.128 loads them
    // pre-packed. Only the two s broadcasts need a mov.b64 {r,r} each.
    const int pe = t >> 4;        // 0..15 -> e0 = 4*pe
    const int pg = t & 15;        // 0..15 -> p0 = 2*pg
    const int e0 = pe * 4;
    const int p0 = pg * 2;

    unsigned long long A0 = 0ull, A1 = 0ull, A2 = 0ull, A3 = 0ull;
    // A0 = {a(e0,p0), a(e1,p0)}, A1 = {a(e0,p1), a(e1,p1)}
    // A2 = {a(e2,p0), a(e3,p0)}, A3 = {a(e2,p1), a(e3,p1)}

    const char* wrow = (const char*)(wT + e0);
    const char* srow = (const char*)(sT + p0);

    #pragma unroll 8
    for (int i = 0; i < 256; ++i) {
        ulonglong2 wv = *(const ulonglong2*)(wrow + (size_t)i * (WSTR * 4));
        float2     sv = *(const float2*)   (srow + (size_t)i * (PSTR * 4));
        unsigned sx = __float_as_uint(sv.x);
        unsigned sy = __float_as_uint(sv.y);
        unsigned long long sxx, syy;
        asm("mov.b64 %0, {%1, %1};" : "=l"(sxx) : "r"(sx));
        asm("mov.b64 %0, {%1, %1};" : "=l"(syy) : "r"(sy));
        FMA_F32X2(A0, wv.x, sxx);
        FMA_F32X2(A1, wv.x, syy);
        FMA_F32X2(A2, wv.y, sxx);
        FMA_F32X2(A3, wv.y, syy);
    }

    float a00, a10, a01, a11, a20, a30, a21, a31;
    asm("mov.b64 {%0, %1}, %2;" : "=f"(a00), "=f"(a10) : "l"(A0));
    asm("mov.b64 {%0, %1}, %2;" : "=f"(a01), "=f"(a11) : "l"(A1));
    asm("mov.b64 {%0, %1}, %2;" : "=f"(a20), "=f"(a30) : "l"(A2));
    asm("mov.b64 {%0, %1}, %2;" : "=f"(a21), "=f"(a31) : "l"(A3));

    float b0 = bs[e0 + 0], b1 = bs[e0 + 1], b2 = bs[e0 + 2], b3 = bs[e0 + 3];
    {
        float4 o;
        o.x = a00 + b0; o.y = a10 + b1; o.z = a20 + b2; o.w = a30 + b3;
        *(float4*)&emb[(size_t)(base_patch + p0) * EMB + e0] = o;
    }
    {
        float4 o;
        o.x = a01 + b0; o.y = a11 + b1; o.z = a21 + b2; o.w = a31 + b3;
        *(float4*)&emb[(size_t)(base_patch + p0 + 1) * EMB + e0] = o;
    }
}

extern "C" void kernel_launch(void* const* d_in, const int* in_sizes, int n_in,
                              void* d_out, int out_size)
{
    const float* x    = (const float*)d_in[0];
    const float* W    = (const float*)d_in[1];
    const float* bias = (const float*)d_in[2];

    float* out  = (float*)d_out;
    float* emb  = out;
    float* frac = out + (size_t)NPATCH * EMB;
    float* harm = frac + NPATCH;

    cudaFuncSetAttribute(fractal_fused_kernel,
                         cudaFuncAttributeMaxDynamicSharedMemorySize, SMEM_BYTES);
    fractal_fused_kernel<<<NPATCH / TP, 256, SMEM_BYTES>>>(x, W, bias, emb, frac, harm);
}